// round 16
// baseline (speedup 1.0000x reference)
#include <cuda_runtime.h>
#include <cuda_bf16.h>
#include <cstdint>
#include <cstddef>

// ---------------------------------------------------------------------------
// Problem constants
// ---------------------------------------------------------------------------
#define NMAX 50000
#define NPAD 50048            // 391 * 128
#define EMAX 400000
#define FD   256
#define NEG_SLOPE 0.2f

// ---------------------------------------------------------------------------
// Scratch (device globals — no runtime allocation allowed)
// feat/el/er are per-relation (x3) so one batched GEMM launch covers a layer.
// ---------------------------------------------------------------------------
__device__ __align__(128) float g_feat[3 * NPAD * FD];
__device__ __align__(128) float g_bufA[NMAX * FD];
__device__ __align__(128) float g_bufB[NMAX * FD];
__device__ __align__(128) float g_el[3 * NPAD * 4];
__device__ __align__(128) float g_er[3 * NPAD * 4];
__device__ __align__(128) float g_ex[3 * EMAX * 4];      // per-edge e / exp values
__device__ __align__(128) int   g_deg   [3 * NMAX];
__device__ __align__(128) int   g_rowptr[3 * NMAX + 1];
__device__ __align__(128) int   g_cursor[3 * NMAX];
__device__ __align__(128) int   g_csrsrc[3 * EMAX];
__device__ __align__(128) int   g_bsum[256];
__device__ __align__(128) int   g_boff[256];
// bf16 split operands
__device__ __align__(128) __nv_bfloat16 g_Ah[NPAD * FD];
__device__ __align__(128) __nv_bfloat16 g_Al[NPAD * FD];
__device__ __align__(128) __nv_bfloat16 g_Wh[9 * FD * FD];   // [mat][n][k]
__device__ __align__(128) __nv_bfloat16 g_Wl[9 * FD * FD];

// ---------------------------------------------------------------------------
// PTX helpers (portable subset only — no sm_103a-suffixed features)
// ---------------------------------------------------------------------------
__device__ __forceinline__ uint32_t smem_u32(const void* p) {
    uint32_t a;
    asm("{ .reg .u64 t; cvta.to.shared.u64 t, %1; cvt.u32.u64 %0, t; }"
        : "=r"(a) : "l"(p));
    return a;
}

#define LDM_X4(r0, r1, r2, r3, a) \
    asm volatile("ldmatrix.sync.aligned.m8n8.x4.shared.b16 {%0,%1,%2,%3}, [%4];" \
                 : "=r"(r0), "=r"(r1), "=r"(r2), "=r"(r3) : "r"(a))
#define MMA_BF16(d, a, b) \
    asm volatile("mma.sync.aligned.m16n8k16.row.col.f32.bf16.bf16.f32 " \
                 "{%0,%1,%2,%3}, {%4,%5,%6,%7}, {%8,%9}, {%0,%1,%2,%3};" \
                 : "+f"((d)[0]), "+f"((d)[1]), "+f"((d)[2]), "+f"((d)[3]) \
                 : "r"((a)[0]), "r"((a)[1]), "r"((a)[2]), "r"((a)[3]), \
                   "r"((b)[0]), "r"((b)[1]))

// ---------------------------------------------------------------------------
// bf16 split conversion kernels
// ---------------------------------------------------------------------------
union U2 { ushort u[4]; uint2 v; };
union U4 { ushort u[8]; uint4 v; };

__global__ void cvt_feat_kernel(const float* __restrict__ in, int n)
{
    int idx = blockIdx.x * blockDim.x + threadIdx.x;   // one float4 per thread
    if (idx >= NPAD * 64) return;
    int row = idx >> 6;
    int c4  = (idx & 63) * 4;
    float4 v = make_float4(0.f, 0.f, 0.f, 0.f);
    if (row < n) v = *(const float4*)(in + (size_t)row * 256 + c4);
    float f[4] = {v.x, v.y, v.z, v.w};
    U2 hi, lo;
#pragma unroll
    for (int j = 0; j < 4; j++) {
        __nv_bfloat16 h = __float2bfloat16(f[j]);
        __nv_bfloat16 l = __float2bfloat16(f[j] - __bfloat162float(h));
        hi.u[j] = *(ushort*)&h;
        lo.u[j] = *(ushort*)&l;
    }
    *(uint2*)(g_Ah + (size_t)row * 256 + c4) = hi.v;
    *(uint2*)(g_Al + (size_t)row * 256 + c4) = lo.v;
}

// weights: input fp32 [k][n] row-major -> output bf16 [n][k] (transposed)
__global__ void cvt_weight_kernel(const float* __restrict__ W0,
                                  const float* __restrict__ W1,
                                  const float* __restrict__ W2)
{
    int idx = blockIdx.x * blockDim.x + threadIdx.x;   // 4 k-elems per thread
    if (idx >= 9 * 256 * 64) return;
    int mat = idx / (256 * 64);
    int rem = idx % (256 * 64);
    int nn  = rem & 255;
    int k0  = (rem >> 8) * 4;
    const float* W = (mat < 3 ? W0 : mat < 6 ? W1 : W2) + (mat % 3) * 65536;
    U2 hi, lo;
#pragma unroll
    for (int j = 0; j < 4; j++) {
        float f = W[(size_t)(k0 + j) * 256 + nn];
        __nv_bfloat16 h = __float2bfloat16(f);
        __nv_bfloat16 l = __float2bfloat16(f - __bfloat162float(h));
        hi.u[j] = *(ushort*)&h;
        lo.u[j] = *(ushort*)&l;
    }
    *(uint2*)(g_Wh + (size_t)mat * 65536 + (size_t)nn * 256 + k0) = hi.v;
    *(uint2*)(g_Wl + (size_t)mat * 65536 + (size_t)nn * 256 + k0) = lo.v;
}

// ---------------------------------------------------------------------------
// mma.sync GEMM, batched over 3 relations via blockIdx.z.
// C(128 x 128 per CTA) = A(128 x 256) * B_r^T(128n x 256k),
// bf16 3-term split (AhBh + AhBl + AlBh), fused el/er epilogue.
// B operand uses X4-paired ldmatrix (two n-tiles per instruction).
// ---------------------------------------------------------------------------
#define STR 72                        // smem row stride in bf16 (144 B)
#define TILE_B (128 * STR)            // bf16 elements per buffer
#define GEMM_SMEM (4 * TILE_B * 2)    // 73728 bytes

__global__ __launch_bounds__(256, 2)
void gemm_mma_kernel(const __nv_bfloat16* __restrict__ Ah,
                     const __nv_bfloat16* __restrict__ Al,
                     const __nv_bfloat16* __restrict__ WhL,   // layer base (3 mats)
                     const __nv_bfloat16* __restrict__ WlL,
                     const float* __restrict__ alwL,          // layer base (3 x 256)
                     const float* __restrict__ arwL,
                     int nrows)
{
    extern __shared__ __nv_bfloat16 sm[];
    __nv_bfloat16* sAh = sm;
    __nv_bfloat16* sAl = sm + TILE_B;
    __nv_bfloat16* sBh = sm + 2 * TILE_B;
    __nv_bfloat16* sBl = sm + 3 * TILE_B;

    const int tid  = threadIdx.x;
    const int wid  = tid >> 5;
    const int lane = tid & 31;
    const int wr   = wid & 1;
    const int wc   = wid >> 1;
    const int brow = blockIdx.x * 128;
    const int bcol = blockIdx.y * 128;
    const int rel  = blockIdx.z;

    const __nv_bfloat16* Bh = WhL + (size_t)rel * 65536;
    const __nv_bfloat16* Bl = WlL + (size_t)rel * 65536;
    const float* alw = alwL + rel * 256;
    const float* arw = arwL + rel * 256;
    float* featOut = g_feat + (size_t)rel * NPAD * FD;
    float* elOut   = g_el   + (size_t)rel * NPAD * 4;
    float* erOut   = g_er   + (size_t)rel * NPAD * 4;

    const uint32_t sAh32 = smem_u32(sAh);
    const uint32_t sAl32 = smem_u32(sAl);
    const uint32_t sBh32 = smem_u32(sBh);
    const uint32_t sBl32 = smem_u32(sBl);

    float acc[4][4][4];
#pragma unroll
    for (int i = 0; i < 4; i++)
#pragma unroll
        for (int j = 0; j < 4; j++)
#pragma unroll
            for (int q = 0; q < 4; q++) acc[i][j][q] = 0.f;

    const uint4* A4h = (const uint4*)Ah;
    const uint4* A4l = (const uint4*)Al;
    const uint4* B4h = (const uint4*)Bh;
    const uint4* B4l = (const uint4*)Bl;

    // ldmatrix lane address components
    const int a_r  = (lane & 7) + ((lane >> 3) & 1) * 8;   // A: 16 rows
    const int a_k8 = (lane >> 4) * 8;                      // A: k half
    const int b_g  = lane >> 3;                            // B x4 group
    const int b_row = (b_g >> 1) * 8 + (lane & 7);         // row within 16-row pair
    const int b_k8  = (b_g & 1) * 8;

    for (int kc = 0; kc < 4; kc++) {
        __syncthreads();
#pragma unroll
        for (int j = 0; j < 4; j++) {
            int i   = tid + j * 256;
            int row = i >> 3, u = i & 7;
            size_t ga = (size_t)(brow + row) * 32 + kc * 8 + u;
            size_t gb = (size_t)(bcol + row) * 32 + kc * 8 + u;
            uint32_t so = (uint32_t)(row * STR + u * 8);
            *(uint4*)(sAh + so) = A4h[ga];
            *(uint4*)(sAl + so) = A4l[ga];
            *(uint4*)(sBh + so) = B4h[gb];
            *(uint4*)(sBl + so) = B4l[gb];
        }
        __syncthreads();

#pragma unroll
        for (int ks = 0; ks < 4; ks++) {
            const int k0 = ks * 16;
            uint32_t afr[4][4], bh[4][2], bl[4][2];
            // A (hi) fragments
#pragma unroll
            for (int ma = 0; ma < 4; ma++) {
                uint32_t addr = sAh32 +
                    (uint32_t)(((wr * 64 + ma * 16 + a_r) * STR + k0 + a_k8) * 2);
                LDM_X4(afr[ma][0], afr[ma][1], afr[ma][2], afr[ma][3], addr);
            }
            // B (hi, lo) fragments — X4-paired, two n-tiles per instruction
#pragma unroll
            for (int pr = 0; pr < 2; pr++) {
                uint32_t off =
                    (uint32_t)(((wc * 32 + pr * 16 + b_row) * STR + k0 + b_k8) * 2);
                LDM_X4(bh[2 * pr][0], bh[2 * pr][1],
                       bh[2 * pr + 1][0], bh[2 * pr + 1][1], sBh32 + off);
                LDM_X4(bl[2 * pr][0], bl[2 * pr][1],
                       bl[2 * pr + 1][0], bl[2 * pr + 1][1], sBl32 + off);
            }
            // AhBh + AhBl
#pragma unroll
            for (int ma = 0; ma < 4; ma++)
#pragma unroll
                for (int na = 0; na < 4; na++) {
                    MMA_BF16(acc[ma][na], afr[ma], bh[na]);
                    MMA_BF16(acc[ma][na], afr[ma], bl[na]);
                }
            // reload A (lo) over the same registers, then AlBh
#pragma unroll
            for (int ma = 0; ma < 4; ma++) {
                uint32_t addr = sAl32 +
                    (uint32_t)(((wr * 64 + ma * 16 + a_r) * STR + k0 + a_k8) * 2);
                LDM_X4(afr[ma][0], afr[ma][1], afr[ma][2], afr[ma][3], addr);
            }
#pragma unroll
            for (int ma = 0; ma < 4; ma++)
#pragma unroll
                for (int na = 0; na < 4; na++)
                    MMA_BF16(acc[ma][na], afr[ma], bh[na]);
        }
    }

    // ---- epilogue: el/er dots + C store ----
    float alv[4][2], arv[4][2];
#pragma unroll
    for (int na = 0; na < 4; na++) {
        int gc = bcol + wc * 32 + na * 8 + (lane & 3) * 2;
        alv[na][0] = alw[gc];     alv[na][1] = alw[gc + 1];
        arv[na][0] = arw[gc];     arv[na][1] = arw[gc + 1];
    }

    float pel[4][2], per_[4][2];
#pragma unroll
    for (int ma = 0; ma < 4; ma++) {
        pel[ma][0] = pel[ma][1] = per_[ma][0] = per_[ma][1] = 0.f;
#pragma unroll
        for (int na = 0; na < 4; na++) {
            pel[ma][0]  += acc[ma][na][0] * alv[na][0] + acc[ma][na][1] * alv[na][1];
            pel[ma][1]  += acc[ma][na][2] * alv[na][0] + acc[ma][na][3] * alv[na][1];
            per_[ma][0] += acc[ma][na][0] * arv[na][0] + acc[ma][na][1] * arv[na][1];
            per_[ma][1] += acc[ma][na][2] * arv[na][0] + acc[ma][na][3] * arv[na][1];
        }
#pragma unroll
        for (int s = 1; s < 4; s <<= 1) {
            pel[ma][0]  += __shfl_xor_sync(0xffffffffu, pel[ma][0],  s);
            pel[ma][1]  += __shfl_xor_sync(0xffffffffu, pel[ma][1],  s);
            per_[ma][0] += __shfl_xor_sync(0xffffffffu, per_[ma][0], s);
            per_[ma][1] += __shfl_xor_sync(0xffffffffu, per_[ma][1], s);
        }
    }

#pragma unroll
    for (int ma = 0; ma < 4; ma++) {
        int r  = wr * 64 + ma * 16 + (lane >> 2);
        int g0 = brow + r;
        int g1 = g0 + 8;
#pragma unroll
        for (int na = 0; na < 4; na++) {
            int c = bcol + wc * 32 + na * 8 + (lane & 3) * 2;
            if (g0 < nrows)
                *(float2*)(featOut + (size_t)g0 * 256 + c) =
                    make_float2(acc[ma][na][0], acc[ma][na][1]);
            if (g1 < nrows)
                *(float2*)(featOut + (size_t)g1 * 256 + c) =
                    make_float2(acc[ma][na][2], acc[ma][na][3]);
        }
    }

    __syncthreads();
    float* sPEl = (float*)sm;
    float* sPEr = (float*)sm + 512;
    if ((lane & 3) == 0) {
#pragma unroll
        for (int ma = 0; ma < 4; ma++) {
            int r = wr * 64 + ma * 16 + (lane >> 2);
            sPEl[wc * 128 + r]     = pel[ma][0];
            sPEl[wc * 128 + r + 8] = pel[ma][1];
            sPEr[wc * 128 + r]     = per_[ma][0];
            sPEr[wc * 128 + r + 8] = per_[ma][1];
        }
    }
    __syncthreads();
    if (tid < 128) {
        int grow = brow + tid;
        if (grow < nrows) {
            int h0 = blockIdx.y * 2;
            elOut[(size_t)grow * 4 + h0]     = sPEl[tid]       + sPEl[128 + tid];
            elOut[(size_t)grow * 4 + h0 + 1] = sPEl[256 + tid] + sPEl[384 + tid];
            erOut[(size_t)grow * 4 + h0]     = sPEr[tid]       + sPEr[128 + tid];
            erOut[(size_t)grow * 4 + h0 + 1] = sPEr[256 + tid] + sPEr[384 + tid];
        }
    }
}

// ---------------------------------------------------------------------------
// CSR build
// ---------------------------------------------------------------------------
__global__ void zero_deg_kernel(int n3)
{
    int i = blockIdx.x * blockDim.x + threadIdx.x;
    if (i < n3) g_deg[i] = 0;
}

__global__ void hist_kernel(const int* __restrict__ dst_all, int E, int n)
{
    int g = blockIdx.x * blockDim.x + threadIdx.x;
    if (g >= 3 * E) return;
    int rel = g / E;
    atomicAdd(&g_deg[rel * n + dst_all[g]], 1);
}

__global__ void scan_local_kernel(int total)
{
    __shared__ int ws[32];
    const int t    = threadIdx.x;          // 1024
    const int lane = t & 31;
    const int wid  = t >> 5;
    const int idx  = blockIdx.x * 1024 + t;

    int v = (idx < total) ? g_deg[idx] : 0;
    int inc = v;
#pragma unroll
    for (int off = 1; off < 32; off <<= 1) {
        int x = __shfl_up_sync(0xffffffffu, inc, off);
        if (lane >= off) inc += x;
    }
    if (lane == 31) ws[wid] = inc;
    __syncthreads();
    if (wid == 0) {
        int w = ws[lane], winc = w;
#pragma unroll
        for (int off = 1; off < 32; off <<= 1) {
            int x = __shfl_up_sync(0xffffffffu, winc, off);
            if (lane >= off) winc += x;
        }
        ws[lane] = winc - w;
    }
    __syncthreads();
    int excl = ws[wid] + inc - v;
    if (idx < total) g_rowptr[idx] = excl;
    if (t == 1023) g_bsum[blockIdx.x] = excl + v;
}

__global__ void scan_bsum_kernel(int nb)
{
    __shared__ int ws[32];
    const int t    = threadIdx.x;          // 256
    const int lane = t & 31;
    const int wid  = t >> 5;
    int v = (t < nb) ? g_bsum[t] : 0;
    int inc = v;
#pragma unroll
    for (int off = 1; off < 32; off <<= 1) {
        int x = __shfl_up_sync(0xffffffffu, inc, off);
        if (lane >= off) inc += x;
    }
    if (lane == 31) ws[wid] = inc;
    __syncthreads();
    if (wid == 0 && lane < 8) {
        int w = ws[lane], winc = w;
#pragma unroll
        for (int off = 1; off < 8; off <<= 1) {
            int x = __shfl_up_sync(0x000000ffu, winc, off);
            if (lane >= off) winc += x;
        }
        ws[lane] = winc - w;
    }
    __syncthreads();
    if (t < nb) g_boff[t] = ws[wid] + inc - v;
}

__global__ void scan_add_kernel(int total, int grand)
{
    int idx = blockIdx.x * 1024 + threadIdx.x;
    if (idx < total) {
        int r = g_rowptr[idx] + g_boff[blockIdx.x];
        g_rowptr[idx] = r;
        g_cursor[idx] = r;
    }
    if (idx == 0) g_rowptr[total] = grand;
}

__global__ void scatter_kernel(const int* __restrict__ src_all,
                               const int* __restrict__ dst_all, int E, int n)
{
    int g = blockIdx.x * blockDim.x + threadIdx.x;
    if (g >= 3 * E) return;
    int rel = g / E;
    int pos = atomicAdd(&g_cursor[rel * n + dst_all[g]], 1);
    g_csrsrc[pos] = src_all[g];
}

// ---------------------------------------------------------------------------
// Node-centric softmax + aggregation. One warp per dst node.
//   mode 0: hacc  = elu(agg+b)/3        (first-executed relation)
//   mode 1: hacc += elu(agg+b)/3
//   mode 2: head-mean of (hacc + elu(agg+b)/3) -> out   (last rel, last layer)
//   mode 3: bf16-split(hacc + elu(agg+b)/3) -> g_Ah/g_Al (last rel, L0/L1)
// ---------------------------------------------------------------------------
__device__ __forceinline__ float lrelu(float e) {
    return e >= 0.f ? e : NEG_SLOPE * e;
}

__global__ __launch_bounds__(256)
void node_agg_kernel(const float* __restrict__ bias,
                     float* __restrict__ hacc,
                     float* __restrict__ outp,
                     const float* __restrict__ featIn,
                     const float* __restrict__ elIn,
                     const float* __restrict__ erIn,
                     int mode, int rbase, int n)
{
    const int warp = (blockIdx.x * blockDim.x + threadIdx.x) >> 5;
    const int lane = threadIdx.x & 31;
    if (warp >= n) return;
    const int node = warp;
    const int beg  = g_rowptr[rbase + node];
    const int end  = g_rowptr[rbase + node + 1];

    const float4 er4 = *(const float4*)(erIn + (size_t)node * 4);

    // ---- pass 1: gather el once, compute e, store raw e, track max ----
    float4 m = make_float4(-3.4e38f, -3.4e38f, -3.4e38f, -3.4e38f);
    for (int i = beg + lane; i < end; i += 32) {
        int s = g_csrsrc[i];
        float4 l = *(const float4*)(elIn + (size_t)s * 4);
        float4 e;
        e.x = lrelu(l.x + er4.x);
        e.y = lrelu(l.y + er4.y);
        e.z = lrelu(l.z + er4.z);
        e.w = lrelu(l.w + er4.w);
        m.x = fmaxf(m.x, e.x);
        m.y = fmaxf(m.y, e.y);
        m.z = fmaxf(m.z, e.z);
        m.w = fmaxf(m.w, e.w);
        *(float4*)(g_ex + (size_t)i * 4) = e;
    }
#pragma unroll
    for (int s_ = 16; s_; s_ >>= 1) {
        m.x = fmaxf(m.x, __shfl_xor_sync(0xffffffffu, m.x, s_));
        m.y = fmaxf(m.y, __shfl_xor_sync(0xffffffffu, m.y, s_));
        m.z = fmaxf(m.z, __shfl_xor_sync(0xffffffffu, m.z, s_));
        m.w = fmaxf(m.w, __shfl_xor_sync(0xffffffffu, m.w, s_));
    }

    // ---- pass 2: sequential re-read of e, exp in place, sum ----
    float4 ss = make_float4(0.f, 0.f, 0.f, 0.f);
    for (int i = beg + lane; i < end; i += 32) {
        float4 e = *(const float4*)(g_ex + (size_t)i * 4);
        float x0 = expf(e.x - m.x);
        float x1 = expf(e.y - m.y);
        float x2 = expf(e.z - m.z);
        float x3 = expf(e.w - m.w);
        ss.x += x0; ss.y += x1; ss.z += x2; ss.w += x3;
        *(float4*)(g_ex + (size_t)i * 4) = make_float4(x0, x1, x2, x3);
    }
#pragma unroll
    for (int s_ = 16; s_; s_ >>= 1) {
        ss.x += __shfl_xor_sync(0xffffffffu, ss.x, s_);
        ss.y += __shfl_xor_sync(0xffffffffu, ss.y, s_);
        ss.z += __shfl_xor_sync(0xffffffffu, ss.z, s_);
        ss.w += __shfl_xor_sync(0xffffffffu, ss.w, s_);
    }

    const int head = lane >> 3;
    float sh = (head == 0) ? ss.x : (head == 1) ? ss.y : (head == 2) ? ss.z : ss.w;
    float rh = 1.f / fmaxf(sh, 1e-9f);

    // ---- pass 3: feature accumulation (whole warp per edge, 2-way unroll) ----
    float4 a0 = make_float4(0.f, 0.f, 0.f, 0.f);
    float4 a1 = make_float4(0.f, 0.f, 0.f, 0.f);
    int i = beg;
    for (; i + 2 <= end; i += 2) {
        int s0 = g_csrsrc[i];
        int s1 = g_csrsrc[i + 1];
        float al0 = g_ex[(size_t)i * 4 + head] * rh;
        float al1 = g_ex[(size_t)(i + 1) * 4 + head] * rh;
        const float4* f0 = (const float4*)(featIn + (size_t)s0 * 256) + lane * 2;
        const float4* f1 = (const float4*)(featIn + (size_t)s1 * 256) + lane * 2;
        float4 u0 = f0[0], u1 = f0[1];
        float4 w0 = f1[0], w1 = f1[1];
        a0.x += u0.x * al0 + w0.x * al1;
        a0.y += u0.y * al0 + w0.y * al1;
        a0.z += u0.z * al0 + w0.z * al1;
        a0.w += u0.w * al0 + w0.w * al1;
        a1.x += u1.x * al0 + w1.x * al1;
        a1.y += u1.y * al0 + w1.y * al1;
        a1.z += u1.z * al0 + w1.z * al1;
        a1.w += u1.w * al0 + w1.w * al1;
    }
    if (i < end) {
        int s0 = g_csrsrc[i];
        float al0 = g_ex[(size_t)i * 4 + head] * rh;
        const float4* f0 = (const float4*)(featIn + (size_t)s0 * 256) + lane * 2;
        float4 u0 = f0[0], u1 = f0[1];
        a0.x += u0.x * al0; a0.y += u0.y * al0;
        a0.z += u0.z * al0; a0.w += u0.w * al0;
        a1.x += u1.x * al0; a1.y += u1.y * al0;
        a1.z += u1.z * al0; a1.w += u1.w * al0;
    }

    // ---- epilogue: bias + elu + /3, cross-relation accumulate ----
    const int col = lane * 8;
    float4 b0 = *(const float4*)(bias + col);
    float4 b1 = *(const float4*)(bias + col + 4);
    float v[8];
    v[0] = a0.x + b0.x; v[1] = a0.y + b0.y; v[2] = a0.z + b0.z; v[3] = a0.w + b0.w;
    v[4] = a1.x + b1.x; v[5] = a1.y + b1.y; v[6] = a1.z + b1.z; v[7] = a1.w + b1.w;
#pragma unroll
    for (int j = 0; j < 8; j++) {
        float t = v[j];
        v[j] = (t > 0.f ? t : expm1f(t)) * (1.f / 3.f);
    }

    float* hp = hacc + (size_t)node * 256 + col;
    if (mode == 0) {
        *(float4*)(hp)     = make_float4(v[0], v[1], v[2], v[3]);
        *(float4*)(hp + 4) = make_float4(v[4], v[5], v[6], v[7]);
    } else if (mode == 1) {
        float4 p0 = *(const float4*)(hp);
        float4 p1 = *(const float4*)(hp + 4);
        *(float4*)(hp)     = make_float4(p0.x + v[0], p0.y + v[1], p0.z + v[2], p0.w + v[3]);
        *(float4*)(hp + 4) = make_float4(p1.x + v[4], p1.y + v[5], p1.z + v[6], p1.w + v[7]);
    } else if (mode == 3) {
        float4 p0 = *(const float4*)(hp);
        float4 p1 = *(const float4*)(hp + 4);
        v[0] += p0.x; v[1] += p0.y; v[2] += p0.z; v[3] += p0.w;
        v[4] += p1.x; v[5] += p1.y; v[6] += p1.z; v[7] += p1.w;
        U4 hi, lo;
#pragma unroll
        for (int j = 0; j < 8; j++) {
            __nv_bfloat16 h = __float2bfloat16(v[j]);
            __nv_bfloat16 l = __float2bfloat16(v[j] - __bfloat162float(h));
            hi.u[j] = *(ushort*)&h;
            lo.u[j] = *(ushort*)&l;
        }
        *(uint4*)(g_Ah + (size_t)node * 256 + col) = hi.v;
        *(uint4*)(g_Al + (size_t)node * 256 + col) = lo.v;
    } else {
        float4 p0 = *(const float4*)(hp);
        float4 p1 = *(const float4*)(hp + 4);
        v[0] += p0.x; v[1] += p0.y; v[2] += p0.z; v[3] += p0.w;
        v[4] += p1.x; v[5] += p1.y; v[6] += p1.z; v[7] += p1.w;
#pragma unroll
        for (int j = 0; j < 8; j++) {
            v[j] += __shfl_xor_sync(0xffffffffu, v[j], 8);
            v[j] += __shfl_xor_sync(0xffffffffu, v[j], 16);
        }
        if (lane < 8) {
            float* o = outp + (size_t)node * 64 + lane * 8;
#pragma unroll
            for (int j = 0; j < 8; j++) o[j] = 0.25f * v[j];
        }
    }
}

// ---------------------------------------------------------------------------
// Host launch — single stream; batched (3-relation) GEMM per layer, aggs run
// in REVERSE relation order (r2 first) so the most recently written feat
// slice is L2-warm. Batched GEMM L0 kept at launch #4 for profiling.
// ---------------------------------------------------------------------------
extern "C" void kernel_launch(void* const* d_in, const int* in_sizes, int n_in,
                              void* d_out, int out_size)
{
    const float* x   = (const float*)d_in[0];
    const int*   src = (const int*)d_in[1];
    const int*   dst = (const int*)d_in[2];
    const float* W[3]  = {(const float*)d_in[3],  (const float*)d_in[7],  (const float*)d_in[11]};
    const float* al[3] = {(const float*)d_in[4],  (const float*)d_in[8],  (const float*)d_in[12]};
    const float* ar[3] = {(const float*)d_in[5],  (const float*)d_in[9],  (const float*)d_in[13]};
    const float* bb[3] = {(const float*)d_in[6],  (const float*)d_in[10], (const float*)d_in[14]};

    const int n = in_sizes[0] / FD;    // 50000
    const int E = in_sizes[1] / 3;     // 400000

    cudaFuncSetAttribute(gemm_mma_kernel,
                         cudaFuncAttributeMaxDynamicSharedMemorySize, GEMM_SMEM);

    float *bufA, *bufB, *pFeat, *pEl, *pEr;
    cudaGetSymbolAddress((void**)&bufA, g_bufA);
    cudaGetSymbolAddress((void**)&bufB, g_bufB);
    cudaGetSymbolAddress((void**)&pFeat, g_feat);
    cudaGetSymbolAddress((void**)&pEl, g_el);
    cudaGetSymbolAddress((void**)&pEr, g_er);
    __nv_bfloat16 *pAh, *pAl, *pWh, *pWl;
    cudaGetSymbolAddress((void**)&pAh, g_Ah);
    cudaGetSymbolAddress((void**)&pAl, g_Al);
    cudaGetSymbolAddress((void**)&pWh, g_Wh);
    cudaGetSymbolAddress((void**)&pWl, g_Wl);

    const int total = 3 * n;
    const int nb    = (total + 1023) / 1024;    // 147 blocks

    const dim3 gemm_grid(NPAD / 128, 2, 3);     // (391, 2, 3) — all relations
    const int  agg_blocks = (n + 7) / 8;

    // #1, #2: operand conversion (batched GEMM L0 depends only on these)
    cvt_weight_kernel<<<(9 * 256 * 64 + 255) / 256, 256>>>(W[0], W[1], W[2]);
    cvt_feat_kernel<<<(NPAD * 64 + 255) / 256, 256>>>(x, n);
    // #3: CSR degree zero (independent)
    zero_deg_kernel<<<(total + 255) / 256, 256>>>(total);
    // #4: batched GEMM for layer 0 — profiled launch
    gemm_mma_kernel<<<gemm_grid, 256, GEMM_SMEM>>>(
        pAh, pAl, pWh, pWl, al[0], ar[0], n);
    // #5..#9: rest of CSR build (needed before first agg)
    hist_kernel<<<(3 * E + 255) / 256, 256>>>(dst, E, n);
    scan_local_kernel<<<nb, 1024>>>(total);
    scan_bsum_kernel<<<1, 256>>>(nb);
    scan_add_kernel<<<nb, 1024>>>(total, 3 * E);
    scatter_kernel<<<(3 * E + 255) / 256, 256>>>(src, dst, E, n);

    float* lay_out[3] = {bufA, bufB, bufA};

    for (int L = 0; L < 3; L++) {
        if (L > 0)   // L0 batched GEMM already launched above
            gemm_mma_kernel<<<gemm_grid, 256, GEMM_SMEM>>>(
                pAh, pAl, pWh + (size_t)L * 3 * 65536, pWl + (size_t)L * 3 * 65536,
                al[L], ar[L], n);
        // aggs in reverse relation order: r2 (L2-warm) -> r1 -> r0
        for (int q = 0; q < 3; q++) {
            int r = 2 - q;                   // relation processed
            int mode;
            if (q == 0)      mode = 0;       // first executed: init hacc
            else if (q == 1) mode = 1;       // accumulate
            else             mode = (L == 2) ? 2 : 3;   // last executed: finalize
            node_agg_kernel<<<agg_blocks, 256>>>(
                bb[L] + r * 256, lay_out[L], (float*)d_out,
                pFeat + (size_t)r * NPAD * FD,
                pEl + (size_t)r * NPAD * 4,
                pEr + (size_t)r * NPAD * 4,
                mode, r * n, n);
        }
    }
}

// round 17
// speedup vs baseline: 1.0085x; 1.0085x over previous
#include <cuda_runtime.h>
#include <cuda_bf16.h>
#include <cstdint>
#include <cstddef>

// ---------------------------------------------------------------------------
// Problem constants
// ---------------------------------------------------------------------------
#define NMAX 50000
#define NPAD 50048            // 391 * 128
#define EMAX 400000
#define FD   256
#define NEG_SLOPE 0.2f

// ---------------------------------------------------------------------------
// Scratch (device globals — no runtime allocation allowed)
// ---------------------------------------------------------------------------
__device__ __align__(128) float g_feat[3 * NPAD * FD];
__device__ __align__(128) float g_bufA[NMAX * FD];
__device__ __align__(128) float g_bufB[NMAX * FD];
__device__ __align__(128) float g_el[3 * NPAD * 4];
__device__ __align__(128) float g_er[3 * NPAD * 4];
__device__ __align__(128) float g_ex[3 * EMAX * 4];
__device__ __align__(128) int   g_deg   [3 * NMAX];
__device__ __align__(128) int   g_rowptr[3 * NMAX + 1];
__device__ __align__(128) int   g_cursor[3 * NMAX];
__device__ __align__(128) int   g_csrsrc[3 * EMAX];
__device__ __align__(128) int   g_bsum[256];
__device__ __align__(128) int   g_boff[256];
__device__ __align__(128) __nv_bfloat16 g_Ah[NPAD * FD];
__device__ __align__(128) __nv_bfloat16 g_Al[NPAD * FD];
__device__ __align__(128) __nv_bfloat16 g_Wh[9 * FD * FD];
__device__ __align__(128) __nv_bfloat16 g_Wl[9 * FD * FD];

// ---------------------------------------------------------------------------
// PTX helpers
// ---------------------------------------------------------------------------
__device__ __forceinline__ uint32_t smem_u32(const void* p) {
    uint32_t a;
    asm("{ .reg .u64 t; cvta.to.shared.u64 t, %1; cvt.u32.u64 %0, t; }"
        : "=r"(a) : "l"(p));
    return a;
}

#define LDM_X4(r0, r1, r2, r3, a) \
    asm volatile("ldmatrix.sync.aligned.m8n8.x4.shared.b16 {%0,%1,%2,%3}, [%4];" \
                 : "=r"(r0), "=r"(r1), "=r"(r2), "=r"(r3) : "r"(a))
#define MMA_BF16(d, a, b) \
    asm volatile("mma.sync.aligned.m16n8k16.row.col.f32.bf16.bf16.f32 " \
                 "{%0,%1,%2,%3}, {%4,%5,%6,%7}, {%8,%9}, {%0,%1,%2,%3};" \
                 : "+f"((d)[0]), "+f"((d)[1]), "+f"((d)[2]), "+f"((d)[3]) \
                 : "r"((a)[0]), "r"((a)[1]), "r"((a)[2]), "r"((a)[3]), \
                   "r"((b)[0]), "r"((b)[1]))

// ---------------------------------------------------------------------------
// bf16 split conversion kernels
// ---------------------------------------------------------------------------
union U2 { ushort u[4]; uint2 v; };
union U4 { ushort u[8]; uint4 v; };

__global__ void cvt_feat_kernel(const float* __restrict__ in, int n)
{
    int idx = blockIdx.x * blockDim.x + threadIdx.x;
    if (idx >= NPAD * 64) return;
    int row = idx >> 6;
    int c4  = (idx & 63) * 4;
    float4 v = make_float4(0.f, 0.f, 0.f, 0.f);
    if (row < n) v = *(const float4*)(in + (size_t)row * 256 + c4);
    float f[4] = {v.x, v.y, v.z, v.w};
    U2 hi, lo;
#pragma unroll
    for (int j = 0; j < 4; j++) {
        __nv_bfloat16 h = __float2bfloat16(f[j]);
        __nv_bfloat16 l = __float2bfloat16(f[j] - __bfloat162float(h));
        hi.u[j] = *(ushort*)&h;
        lo.u[j] = *(ushort*)&l;
    }
    *(uint2*)(g_Ah + (size_t)row * 256 + c4) = hi.v;
    *(uint2*)(g_Al + (size_t)row * 256 + c4) = lo.v;
}

__global__ void cvt_weight_kernel(const float* __restrict__ W0,
                                  const float* __restrict__ W1,
                                  const float* __restrict__ W2)
{
    int idx = blockIdx.x * blockDim.x + threadIdx.x;
    if (idx >= 9 * 256 * 64) return;
    int mat = idx / (256 * 64);
    int rem = idx % (256 * 64);
    int nn  = rem & 255;
    int k0  = (rem >> 8) * 4;
    const float* W = (mat < 3 ? W0 : mat < 6 ? W1 : W2) + (mat % 3) * 65536;
    U2 hi, lo;
#pragma unroll
    for (int j = 0; j < 4; j++) {
        float f = W[(size_t)(k0 + j) * 256 + nn];
        __nv_bfloat16 h = __float2bfloat16(f);
        __nv_bfloat16 l = __float2bfloat16(f - __bfloat162float(h));
        hi.u[j] = *(ushort*)&h;
        lo.u[j] = *(ushort*)&l;
    }
    *(uint2*)(g_Wh + (size_t)mat * 65536 + (size_t)nn * 256 + k0) = hi.v;
    *(uint2*)(g_Wl + (size_t)mat * 65536 + (size_t)nn * 256 + k0) = lo.v;
}

// ---------------------------------------------------------------------------
// mma.sync GEMM, batched over 3 relations via blockIdx.z.
// ---------------------------------------------------------------------------
#define STR 72
#define TILE_B (128 * STR)
#define GEMM_SMEM (4 * TILE_B * 2)

__global__ __launch_bounds__(256, 2)
void gemm_mma_kernel(const __nv_bfloat16* __restrict__ Ah,
                     const __nv_bfloat16* __restrict__ Al,
                     const __nv_bfloat16* __restrict__ WhL,
                     const __nv_bfloat16* __restrict__ WlL,
                     const float* __restrict__ alwL,
                     const float* __restrict__ arwL,
                     int nrows)
{
    extern __shared__ __nv_bfloat16 sm[];
    __nv_bfloat16* sAh = sm;
    __nv_bfloat16* sAl = sm + TILE_B;
    __nv_bfloat16* sBh = sm + 2 * TILE_B;
    __nv_bfloat16* sBl = sm + 3 * TILE_B;

    const int tid  = threadIdx.x;
    const int wid  = tid >> 5;
    const int lane = tid & 31;
    const int wr   = wid & 1;
    const int wc   = wid >> 1;
    const int brow = blockIdx.x * 128;
    const int bcol = blockIdx.y * 128;
    const int rel  = blockIdx.z;

    const __nv_bfloat16* Bh = WhL + (size_t)rel * 65536;
    const __nv_bfloat16* Bl = WlL + (size_t)rel * 65536;
    const float* alw = alwL + rel * 256;
    const float* arw = arwL + rel * 256;
    float* featOut = g_feat + (size_t)rel * NPAD * FD;
    float* elOut   = g_el   + (size_t)rel * NPAD * 4;
    float* erOut   = g_er   + (size_t)rel * NPAD * 4;

    const uint32_t sAh32 = smem_u32(sAh);
    const uint32_t sAl32 = smem_u32(sAl);
    const uint32_t sBh32 = smem_u32(sBh);
    const uint32_t sBl32 = smem_u32(sBl);

    float acc[4][4][4];
#pragma unroll
    for (int i = 0; i < 4; i++)
#pragma unroll
        for (int j = 0; j < 4; j++)
#pragma unroll
            for (int q = 0; q < 4; q++) acc[i][j][q] = 0.f;

    const uint4* A4h = (const uint4*)Ah;
    const uint4* A4l = (const uint4*)Al;
    const uint4* B4h = (const uint4*)Bh;
    const uint4* B4l = (const uint4*)Bl;

    const int a_r  = (lane & 7) + ((lane >> 3) & 1) * 8;
    const int a_k8 = (lane >> 4) * 8;
    const int b_g  = lane >> 3;
    const int b_row = (b_g >> 1) * 8 + (lane & 7);
    const int b_k8  = (b_g & 1) * 8;

    for (int kc = 0; kc < 4; kc++) {
        __syncthreads();
#pragma unroll
        for (int j = 0; j < 4; j++) {
            int i   = tid + j * 256;
            int row = i >> 3, u = i & 7;
            size_t ga = (size_t)(brow + row) * 32 + kc * 8 + u;
            size_t gb = (size_t)(bcol + row) * 32 + kc * 8 + u;
            uint32_t so = (uint32_t)(row * STR + u * 8);
            *(uint4*)(sAh + so) = A4h[ga];
            *(uint4*)(sAl + so) = A4l[ga];
            *(uint4*)(sBh + so) = B4h[gb];
            *(uint4*)(sBl + so) = B4l[gb];
        }
        __syncthreads();

#pragma unroll
        for (int ks = 0; ks < 4; ks++) {
            const int k0 = ks * 16;
            uint32_t afr[4][4], bh[4][2], bl[4][2];
#pragma unroll
            for (int ma = 0; ma < 4; ma++) {
                uint32_t addr = sAh32 +
                    (uint32_t)(((wr * 64 + ma * 16 + a_r) * STR + k0 + a_k8) * 2);
                LDM_X4(afr[ma][0], afr[ma][1], afr[ma][2], afr[ma][3], addr);
            }
#pragma unroll
            for (int pr = 0; pr < 2; pr++) {
                uint32_t off =
                    (uint32_t)(((wc * 32 + pr * 16 + b_row) * STR + k0 + b_k8) * 2);
                LDM_X4(bh[2 * pr][0], bh[2 * pr][1],
                       bh[2 * pr + 1][0], bh[2 * pr + 1][1], sBh32 + off);
                LDM_X4(bl[2 * pr][0], bl[2 * pr][1],
                       bl[2 * pr + 1][0], bl[2 * pr + 1][1], sBl32 + off);
            }
#pragma unroll
            for (int ma = 0; ma < 4; ma++)
#pragma unroll
                for (int na = 0; na < 4; na++) {
                    MMA_BF16(acc[ma][na], afr[ma], bh[na]);
                    MMA_BF16(acc[ma][na], afr[ma], bl[na]);
                }
#pragma unroll
            for (int ma = 0; ma < 4; ma++) {
                uint32_t addr = sAl32 +
                    (uint32_t)(((wr * 64 + ma * 16 + a_r) * STR + k0 + a_k8) * 2);
                LDM_X4(afr[ma][0], afr[ma][1], afr[ma][2], afr[ma][3], addr);
            }
#pragma unroll
            for (int ma = 0; ma < 4; ma++)
#pragma unroll
                for (int na = 0; na < 4; na++)
                    MMA_BF16(acc[ma][na], afr[ma], bh[na]);
        }
    }

    // ---- epilogue: el/er dots + C store ----
    float alv[4][2], arv[4][2];
#pragma unroll
    for (int na = 0; na < 4; na++) {
        int gc = bcol + wc * 32 + na * 8 + (lane & 3) * 2;
        alv[na][0] = alw[gc];     alv[na][1] = alw[gc + 1];
        arv[na][0] = arw[gc];     arv[na][1] = arw[gc + 1];
    }

    float pel[4][2], per_[4][2];
#pragma unroll
    for (int ma = 0; ma < 4; ma++) {
        pel[ma][0] = pel[ma][1] = per_[ma][0] = per_[ma][1] = 0.f;
#pragma unroll
        for (int na = 0; na < 4; na++) {
            pel[ma][0]  += acc[ma][na][0] * alv[na][0] + acc[ma][na][1] * alv[na][1];
            pel[ma][1]  += acc[ma][na][2] * alv[na][0] + acc[ma][na][3] * alv[na][1];
            per_[ma][0] += acc[ma][na][0] * arv[na][0] + acc[ma][na][1] * arv[na][1];
            per_[ma][1] += acc[ma][na][2] * arv[na][0] + acc[ma][na][3] * arv[na][1];
        }
#pragma unroll
        for (int s = 1; s < 4; s <<= 1) {
            pel[ma][0]  += __shfl_xor_sync(0xffffffffu, pel[ma][0],  s);
            pel[ma][1]  += __shfl_xor_sync(0xffffffffu, pel[ma][1],  s);
            per_[ma][0] += __shfl_xor_sync(0xffffffffu, per_[ma][0], s);
            per_[ma][1] += __shfl_xor_sync(0xffffffffu, per_[ma][1], s);
        }
    }

#pragma unroll
    for (int ma = 0; ma < 4; ma++) {
        int r  = wr * 64 + ma * 16 + (lane >> 2);
        int g0 = brow + r;
        int g1 = g0 + 8;
#pragma unroll
        for (int na = 0; na < 4; na++) {
            int c = bcol + wc * 32 + na * 8 + (lane & 3) * 2;
            if (g0 < nrows)
                *(float2*)(featOut + (size_t)g0 * 256 + c) =
                    make_float2(acc[ma][na][0], acc[ma][na][1]);
            if (g1 < nrows)
                *(float2*)(featOut + (size_t)g1 * 256 + c) =
                    make_float2(acc[ma][na][2], acc[ma][na][3]);
        }
    }

    __syncthreads();
    float* sPEl = (float*)sm;
    float* sPEr = (float*)sm + 512;
    if ((lane & 3) == 0) {
#pragma unroll
        for (int ma = 0; ma < 4; ma++) {
            int r = wr * 64 + ma * 16 + (lane >> 2);
            sPEl[wc * 128 + r]     = pel[ma][0];
            sPEl[wc * 128 + r + 8] = pel[ma][1];
            sPEr[wc * 128 + r]     = per_[ma][0];
            sPEr[wc * 128 + r + 8] = per_[ma][1];
        }
    }
    __syncthreads();
    if (tid < 128) {
        int grow = brow + tid;
        if (grow < nrows) {
            int h0 = blockIdx.y * 2;
            elOut[(size_t)grow * 4 + h0]     = sPEl[tid]       + sPEl[128 + tid];
            elOut[(size_t)grow * 4 + h0 + 1] = sPEl[256 + tid] + sPEl[384 + tid];
            erOut[(size_t)grow * 4 + h0]     = sPEr[tid]       + sPEr[128 + tid];
            erOut[(size_t)grow * 4 + h0 + 1] = sPEr[256 + tid] + sPEr[384 + tid];
        }
    }
}

// ---------------------------------------------------------------------------
// CSR build
// ---------------------------------------------------------------------------
__global__ void zero_deg_kernel(int n3)
{
    int i = blockIdx.x * blockDim.x + threadIdx.x;
    if (i < n3) g_deg[i] = 0;
}

__global__ void hist_kernel(const int* __restrict__ dst_all, int E, int n)
{
    int g = blockIdx.x * blockDim.x + threadIdx.x;
    if (g >= 3 * E) return;
    int rel = g / E;
    atomicAdd(&g_deg[rel * n + dst_all[g]], 1);
}

__global__ void scan_local_kernel(int total)
{
    __shared__ int ws[32];
    const int t    = threadIdx.x;
    const int lane = t & 31;
    const int wid  = t >> 5;
    const int idx  = blockIdx.x * 1024 + t;

    int v = (idx < total) ? g_deg[idx] : 0;
    int inc = v;
#pragma unroll
    for (int off = 1; off < 32; off <<= 1) {
        int x = __shfl_up_sync(0xffffffffu, inc, off);
        if (lane >= off) inc += x;
    }
    if (lane == 31) ws[wid] = inc;
    __syncthreads();
    if (wid == 0) {
        int w = ws[lane], winc = w;
#pragma unroll
        for (int off = 1; off < 32; off <<= 1) {
            int x = __shfl_up_sync(0xffffffffu, winc, off);
            if (lane >= off) winc += x;
        }
        ws[lane] = winc - w;
    }
    __syncthreads();
    int excl = ws[wid] + inc - v;
    if (idx < total) g_rowptr[idx] = excl;
    if (t == 1023) g_bsum[blockIdx.x] = excl + v;
}

__global__ void scan_bsum_kernel(int nb)
{
    __shared__ int ws[32];
    const int t    = threadIdx.x;
    const int lane = t & 31;
    const int wid  = t >> 5;
    int v = (t < nb) ? g_bsum[t] : 0;
    int inc = v;
#pragma unroll
    for (int off = 1; off < 32; off <<= 1) {
        int x = __shfl_up_sync(0xffffffffu, inc, off);
        if (lane >= off) inc += x;
    }
    if (lane == 31) ws[wid] = inc;
    __syncthreads();
    if (wid == 0 && lane < 8) {
        int w = ws[lane], winc = w;
#pragma unroll
        for (int off = 1; off < 8; off <<= 1) {
            int x = __shfl_up_sync(0x000000ffu, winc, off);
            if (lane >= off) winc += x;
        }
        ws[lane] = winc - w;
    }
    __syncthreads();
    if (t < nb) g_boff[t] = ws[wid] + inc - v;
}

__global__ void scan_add_kernel(int total, int grand)
{
    int idx = blockIdx.x * 1024 + threadIdx.x;
    if (idx < total) {
        int r = g_rowptr[idx] + g_boff[blockIdx.x];
        g_rowptr[idx] = r;
        g_cursor[idx] = r;
    }
    if (idx == 0) g_rowptr[total] = grand;
}

__global__ void scatter_kernel(const int* __restrict__ src_all,
                               const int* __restrict__ dst_all, int E, int n)
{
    int g = blockIdx.x * blockDim.x + threadIdx.x;
    if (g >= 3 * E) return;
    int rel = g / E;
    int pos = atomicAdd(&g_cursor[rel * n + dst_all[g]], 1);
    g_csrsrc[pos] = src_all[g];
}

// ---------------------------------------------------------------------------
// Node-centric softmax + aggregation. One warp per dst node.
//   mode 0: hacc  = elu(agg+b)/3        (first-executed relation)
//   mode 1: hacc += elu(agg+b)/3
//   mode 2: head-mean of (hacc + elu(agg+b)/3) -> out   (last rel, last layer)
//   mode 3: bf16-split(hacc + elu(agg+b)/3) -> g_Ah/g_Al (last rel, L0/L1)
// ---------------------------------------------------------------------------
__device__ __forceinline__ float lrelu(float e) {
    return e >= 0.f ? e : NEG_SLOPE * e;
}

__global__ __launch_bounds__(256)
void node_agg_kernel(const float* __restrict__ bias,
                     float* __restrict__ hacc,
                     float* __restrict__ outp,
                     const float* __restrict__ featIn,
                     const float* __restrict__ elIn,
                     const float* __restrict__ erIn,
                     int mode, int rbase, int n)
{
    const int warp = (blockIdx.x * blockDim.x + threadIdx.x) >> 5;
    const int lane = threadIdx.x & 31;
    if (warp >= n) return;
    const int node = warp;
    const int beg  = g_rowptr[rbase + node];
    const int end  = g_rowptr[rbase + node + 1];

    const float4 er4 = *(const float4*)(erIn + (size_t)node * 4);

    // ---- pass 1: gather el once, compute e, store raw e, track max ----
    float4 m = make_float4(-3.4e38f, -3.4e38f, -3.4e38f, -3.4e38f);
    for (int i = beg + lane; i < end; i += 32) {
        int s = g_csrsrc[i];
        float4 l = *(const float4*)(elIn + (size_t)s * 4);
        float4 e;
        e.x = lrelu(l.x + er4.x);
        e.y = lrelu(l.y + er4.y);
        e.z = lrelu(l.z + er4.z);
        e.w = lrelu(l.w + er4.w);
        m.x = fmaxf(m.x, e.x);
        m.y = fmaxf(m.y, e.y);
        m.z = fmaxf(m.z, e.z);
        m.w = fmaxf(m.w, e.w);
        *(float4*)(g_ex + (size_t)i * 4) = e;
    }
#pragma unroll
    for (int s_ = 16; s_; s_ >>= 1) {
        m.x = fmaxf(m.x, __shfl_xor_sync(0xffffffffu, m.x, s_));
        m.y = fmaxf(m.y, __shfl_xor_sync(0xffffffffu, m.y, s_));
        m.z = fmaxf(m.z, __shfl_xor_sync(0xffffffffu, m.z, s_));
        m.w = fmaxf(m.w, __shfl_xor_sync(0xffffffffu, m.w, s_));
    }

    // ---- pass 2: sequential re-read of e, exp in place, sum ----
    float4 ss = make_float4(0.f, 0.f, 0.f, 0.f);
    for (int i = beg + lane; i < end; i += 32) {
        float4 e = *(const float4*)(g_ex + (size_t)i * 4);
        float x0 = expf(e.x - m.x);
        float x1 = expf(e.y - m.y);
        float x2 = expf(e.z - m.z);
        float x3 = expf(e.w - m.w);
        ss.x += x0; ss.y += x1; ss.z += x2; ss.w += x3;
        *(float4*)(g_ex + (size_t)i * 4) = make_float4(x0, x1, x2, x3);
    }
#pragma unroll
    for (int s_ = 16; s_; s_ >>= 1) {
        ss.x += __shfl_xor_sync(0xffffffffu, ss.x, s_);
        ss.y += __shfl_xor_sync(0xffffffffu, ss.y, s_);
        ss.z += __shfl_xor_sync(0xffffffffu, ss.z, s_);
        ss.w += __shfl_xor_sync(0xffffffffu, ss.w, s_);
    }

    const int head = lane >> 3;
    float sh = (head == 0) ? ss.x : (head == 1) ? ss.y : (head == 2) ? ss.z : ss.w;
    float rh = 1.f / fmaxf(sh, 1e-9f);

    // ---- pass 3: feature accumulation (whole warp per edge, 4-way unroll) ----
    float4 a0 = make_float4(0.f, 0.f, 0.f, 0.f);
    float4 a1 = make_float4(0.f, 0.f, 0.f, 0.f);
    int i = beg;
    for (; i + 4 <= end; i += 4) {
        int s0 = g_csrsrc[i];
        int s1 = g_csrsrc[i + 1];
        int s2 = g_csrsrc[i + 2];
        int s3 = g_csrsrc[i + 3];
        float al0 = g_ex[(size_t)i * 4 + head] * rh;
        float al1 = g_ex[(size_t)(i + 1) * 4 + head] * rh;
        float al2 = g_ex[(size_t)(i + 2) * 4 + head] * rh;
        float al3 = g_ex[(size_t)(i + 3) * 4 + head] * rh;
        const float4* f0 = (const float4*)(featIn + (size_t)s0 * 256) + lane * 2;
        const float4* f1 = (const float4*)(featIn + (size_t)s1 * 256) + lane * 2;
        const float4* f2 = (const float4*)(featIn + (size_t)s2 * 256) + lane * 2;
        const float4* f3 = (const float4*)(featIn + (size_t)s3 * 256) + lane * 2;
        float4 u00 = f0[0], u01 = f0[1];
        float4 u10 = f1[0], u11 = f1[1];
        float4 u20 = f2[0], u21 = f2[1];
        float4 u30 = f3[0], u31 = f3[1];
        a0.x += u00.x * al0 + u10.x * al1 + u20.x * al2 + u30.x * al3;
        a0.y += u00.y * al0 + u10.y * al1 + u20.y * al2 + u30.y * al3;
        a0.z += u00.z * al0 + u10.z * al1 + u20.z * al2 + u30.z * al3;
        a0.w += u00.w * al0 + u10.w * al1 + u20.w * al2 + u30.w * al3;
        a1.x += u01.x * al0 + u11.x * al1 + u21.x * al2 + u31.x * al3;
        a1.y += u01.y * al0 + u11.y * al1 + u21.y * al2 + u31.y * al3;
        a1.z += u01.z * al0 + u11.z * al1 + u21.z * al2 + u31.z * al3;
        a1.w += u01.w * al0 + u11.w * al1 + u21.w * al2 + u31.w * al3;
    }
    for (; i < end; i++) {
        int s0 = g_csrsrc[i];
        float al0 = g_ex[(size_t)i * 4 + head] * rh;
        const float4* f0 = (const float4*)(featIn + (size_t)s0 * 256) + lane * 2;
        float4 u0 = f0[0], u1 = f0[1];
        a0.x += u0.x * al0; a0.y += u0.y * al0;
        a0.z += u0.z * al0; a0.w += u0.w * al0;
        a1.x += u1.x * al0; a1.y += u1.y * al0;
        a1.z += u1.z * al0; a1.w += u1.w * al0;
    }

    // ---- epilogue: bias + elu + /3, cross-relation accumulate ----
    const int col = lane * 8;
    float4 b0 = *(const float4*)(bias + col);
    float4 b1 = *(const float4*)(bias + col + 4);
    float v[8];
    v[0] = a0.x + b0.x; v[1] = a0.y + b0.y; v[2] = a0.z + b0.z; v[3] = a0.w + b0.w;
    v[4] = a1.x + b1.x; v[5] = a1.y + b1.y; v[6] = a1.z + b1.z; v[7] = a1.w + b1.w;
#pragma unroll
    for (int j = 0; j < 8; j++) {
        float t = v[j];
        v[j] = (t > 0.f ? t : expm1f(t)) * (1.f / 3.f);
    }

    float* hp = hacc + (size_t)node * 256 + col;
    if (mode == 0) {
        *(float4*)(hp)     = make_float4(v[0], v[1], v[2], v[3]);
        *(float4*)(hp + 4) = make_float4(v[4], v[5], v[6], v[7]);
    } else if (mode == 1) {
        float4 p0 = *(const float4*)(hp);
        float4 p1 = *(const float4*)(hp + 4);
        *(float4*)(hp)     = make_float4(p0.x + v[0], p0.y + v[1], p0.z + v[2], p0.w + v[3]);
        *(float4*)(hp + 4) = make_float4(p1.x + v[4], p1.y + v[5], p1.z + v[6], p1.w + v[7]);
    } else if (mode == 3) {
        float4 p0 = *(const float4*)(hp);
        float4 p1 = *(const float4*)(hp + 4);
        v[0] += p0.x; v[1] += p0.y; v[2] += p0.z; v[3] += p0.w;
        v[4] += p1.x; v[5] += p1.y; v[6] += p1.z; v[7] += p1.w;
        U4 hi, lo;
#pragma unroll
        for (int j = 0; j < 8; j++) {
            __nv_bfloat16 h = __float2bfloat16(v[j]);
            __nv_bfloat16 l = __float2bfloat16(v[j] - __bfloat162float(h));
            hi.u[j] = *(ushort*)&h;
            lo.u[j] = *(ushort*)&l;
        }
        *(uint4*)(g_Ah + (size_t)node * 256 + col) = hi.v;
        *(uint4*)(g_Al + (size_t)node * 256 + col) = lo.v;
    } else {
        float4 p0 = *(const float4*)(hp);
        float4 p1 = *(const float4*)(hp + 4);
        v[0] += p0.x; v[1] += p0.y; v[2] += p0.z; v[3] += p0.w;
        v[4] += p1.x; v[5] += p1.y; v[6] += p1.z; v[7] += p1.w;
#pragma unroll
        for (int j = 0; j < 8; j++) {
            v[j] += __shfl_xor_sync(0xffffffffu, v[j], 8);
            v[j] += __shfl_xor_sync(0xffffffffu, v[j], 16);
        }
        if (lane < 8) {
            float* o = outp + (size_t)node * 64 + lane * 8;
#pragma unroll
            for (int j = 0; j < 8; j++) o[j] = 0.25f * v[j];
        }
    }
}

// ---------------------------------------------------------------------------
// Host launch — CSR build forked onto a side stream so it overlaps the
// cvt + GEMM(L0) work on the main stream; first agg waits on scatter-done.
// ---------------------------------------------------------------------------
extern "C" void kernel_launch(void* const* d_in, const int* in_sizes, int n_in,
                              void* d_out, int out_size)
{
    const float* x   = (const float*)d_in[0];
    const int*   src = (const int*)d_in[1];
    const int*   dst = (const int*)d_in[2];
    const float* W[3]  = {(const float*)d_in[3],  (const float*)d_in[7],  (const float*)d_in[11]};
    const float* al[3] = {(const float*)d_in[4],  (const float*)d_in[8],  (const float*)d_in[12]};
    const float* ar[3] = {(const float*)d_in[5],  (const float*)d_in[9],  (const float*)d_in[13]};
    const float* bb[3] = {(const float*)d_in[6],  (const float*)d_in[10], (const float*)d_in[14]};

    const int n = in_sizes[0] / FD;    // 50000
    const int E = in_sizes[1] / 3;     // 400000

    cudaFuncSetAttribute(gemm_mma_kernel,
                         cudaFuncAttributeMaxDynamicSharedMemorySize, GEMM_SMEM);

    // one-time host-side resources (handles only; no device allocation)
    static cudaStream_t sCsr = nullptr;
    static cudaEvent_t  evFork = nullptr, evCsr = nullptr;
    if (!sCsr) {
        cudaStreamCreateWithFlags(&sCsr, cudaStreamNonBlocking);
        cudaEventCreateWithFlags(&evFork, cudaEventDisableTiming);
        cudaEventCreateWithFlags(&evCsr,  cudaEventDisableTiming);
    }

    float *bufA, *bufB, *pFeat, *pEl, *pEr;
    cudaGetSymbolAddress((void**)&bufA, g_bufA);
    cudaGetSymbolAddress((void**)&bufB, g_bufB);
    cudaGetSymbolAddress((void**)&pFeat, g_feat);
    cudaGetSymbolAddress((void**)&pEl, g_el);
    cudaGetSymbolAddress((void**)&pEr, g_er);
    __nv_bfloat16 *pAh, *pAl, *pWh, *pWl;
    cudaGetSymbolAddress((void**)&pAh, g_Ah);
    cudaGetSymbolAddress((void**)&pAl, g_Al);
    cudaGetSymbolAddress((void**)&pWh, g_Wh);
    cudaGetSymbolAddress((void**)&pWl, g_Wl);

    const int total = 3 * n;
    const int nb    = (total + 1023) / 1024;    // 147 blocks

    const dim3 gemm_grid(NPAD / 128, 2, 3);
    const int  agg_blocks = (n + 7) / 8;

    // ---- fork: CSR build on side stream (depends only on src/dst) ----
    cudaEventRecord(evFork, 0);
    cudaStreamWaitEvent(sCsr, evFork, 0);
    zero_deg_kernel<<<(total + 255) / 256, 256, 0, sCsr>>>(total);
    hist_kernel<<<(3 * E + 255) / 256, 256, 0, sCsr>>>(dst, E, n);
    scan_local_kernel<<<nb, 1024, 0, sCsr>>>(total);
    scan_bsum_kernel<<<1, 256, 0, sCsr>>>(nb);
    scan_add_kernel<<<nb, 1024, 0, sCsr>>>(total, 3 * E);
    scatter_kernel<<<(3 * E + 255) / 256, 256, 0, sCsr>>>(src, dst, E, n);
    cudaEventRecord(evCsr, sCsr);

    // ---- main stream: conversions + batched GEMM L0 ----
    cvt_weight_kernel<<<(9 * 256 * 64 + 255) / 256, 256>>>(W[0], W[1], W[2]);
    cvt_feat_kernel<<<(NPAD * 64 + 255) / 256, 256>>>(x, n);
    gemm_mma_kernel<<<gemm_grid, 256, GEMM_SMEM>>>(
        pAh, pAl, pWh, pWl, al[0], ar[0], n);

    // join: aggs need the CSR
    cudaStreamWaitEvent(0, evCsr, 0);

    float* lay_out[3] = {bufA, bufB, bufA};

    for (int L = 0; L < 3; L++) {
        if (L > 0)
            gemm_mma_kernel<<<gemm_grid, 256, GEMM_SMEM>>>(
                pAh, pAl, pWh + (size_t)L * 3 * 65536, pWl + (size_t)L * 3 * 65536,
                al[L], ar[L], n);
        // aggs in reverse relation order: r2 (L2-warm) -> r1 -> r0
        for (int q = 0; q < 3; q++) {
            int r = 2 - q;
            int mode;
            if (q == 0)      mode = 0;
            else if (q == 1) mode = 1;
            else             mode = (L == 2) ? 2 : 3;
            node_agg_kernel<<<agg_blocks, 256>>>(
                bb[L] + r * 256, lay_out[L], (float*)d_out,
                pFeat + (size_t)r * NPAD * FD,
                pEl + (size_t)r * NPAD * 4,
                pEr + (size_t)r * NPAD * 4,
                mode, r * n, n);
        }
    }
}